// round 15
// baseline (speedup 1.0000x reference)
#include <cuda_runtime.h>
#include <cuda_fp16.h>
#include <cstdint>

#define NNODE 4096
#define FD 256
#define HD 256
#define KEXP 3
#define TSTEP 5
#define G4 1024
#define SIG_LO 10
#define SIG_HI 253   // F_DIM - END

#define NF  ((size_t)NNODE * FD)     // 1048576
#define NG4 ((size_t)NNODE * G4)

// ---------------- scratch (device globals: no allocation allowed) ----------------
__device__ __half g_Ah[KEXP][(size_t)NNODE * NNODE];  // a_bin + I, {0,1,2} exact
__device__ float  g_dinv[KEXP][NNODE];
__device__ __half g_yT[KEXP][(size_t)HD * NNODE];     // (dinv_j * x@w)^T  [h][n]
__device__ __half g_xt[KEXP][NF];                     // gnn_out, half, row-major
__device__ __half g_gx[KEXP][NG4];                    // pair-block gate layout, half
__device__ __half g_h[2][KEXP][NF];                   // double-buffered hidden
__device__ float  g_c[KEXP][NF];
__device__ float  g_delta[KEXP][NF];
__device__ __half g_wih_p[KEXP][G4 * HD];             // pair-block permuted, half
__device__ __half g_whh_p[KEXP][G4 * HD];
__device__ float  g_b_p[KEXP][G4];                    // b_ih + b_hh permuted
__device__ __half g_wT[KEXP][FD * HD];                // gnn_w transposed [h][f]
__device__ __half g_fcw[KEXP][FD * HD];               // fc_w cast (already [n][k])
__device__ __half g_xh[NF];                           // x cast

// hardware tanh (sm_75+): 1 MUFU op, abs err ~1e-5
__device__ __forceinline__ float ftanh(float x) {
    float y;
    asm("tanh.approx.f32 %0, %1;" : "=f"(y) : "f"(x));
    return y;
}
__device__ __forceinline__ float fsig(float x) {
    return fmaf(ftanh(x * 0.5f), 0.5f, 0.5f);
}

__device__ __forceinline__ void mma_f16(float c[4], const uint32_t a[4], const uint32_t b[2]) {
    asm volatile(
        "mma.sync.aligned.m16n8k16.row.col.f32.f16.f16.f32 "
        "{%0,%1,%2,%3}, {%4,%5,%6,%7}, {%8,%9}, {%0,%1,%2,%3};"
        : "+f"(c[0]), "+f"(c[1]), "+f"(c[2]), "+f"(c[3])
        : "r"(a[0]), "r"(a[1]), "r"(a[2]), "r"(a[3]), "r"(b[0]), "r"(b[1]));
}

__device__ __forceinline__ void cp16(void* sdst, const void* gsrc) {
    uint32_t s = (uint32_t)__cvta_generic_to_shared(sdst);
    asm volatile("cp.async.cg.shared.global [%0], [%1], 16;\n" :: "r"(s), "l"(gsrc));
}
__device__ __forceinline__ void cp_commit() { asm volatile("cp.async.commit_group;\n"); }
template <int N>
__device__ __forceinline__ void cp_wait() { asm volatile("cp.async.wait_group %0;\n" :: "n"(N)); }

__device__ __forceinline__ void ldsm4(uint32_t& r0, uint32_t& r1, uint32_t& r2, uint32_t& r3,
                                      const __half* p) {
    uint32_t a = (uint32_t)__cvta_generic_to_shared(p);
    asm volatile("ldmatrix.sync.aligned.m8n8.x4.shared.b16 {%0,%1,%2,%3}, [%4];"
                 : "=r"(r0), "=r"(r1), "=r"(r2), "=r"(r3) : "r"(a));
}

__device__ __forceinline__ uint32_t h2bits(__half2 h) { return *(uint32_t*)&h; }

// ---------------- all conversions in one kernel (standalone) ----------------
__global__ void conv_all(const float* __restrict__ x,
                         const float* __restrict__ gnn_w, const float* __restrict__ fc_w,
                         const float* __restrict__ w_ih, const float* __restrict__ w_hh,
                         const float* __restrict__ b_ih, const float* __restrict__ b_hh) {
    int idx = blockIdx.x * 256 + threadIdx.x;          // grid covers NF
    g_xh[idx] = __float2half(x[idx]);
    if (idx < KEXP * FD * HD) {
        int k = idx / (FD * HD);
        int rem = idx - k * (FD * HD);
        int f = rem / HD, h = rem % HD;
        g_wT[k][h * FD + f] = __float2half(gnn_w[idx]);
        g_fcw[k][rem] = __float2half(fc_w[idx]);
    }
    if (idx < KEXP * G4 * HD) {
        // pair-block gate permutation:
        // out row j: group=j>>4, r=j&15.
        //  r<8 : f = group*4 + (r>>1), gate = r&1
        //  r>=8: f = group*4 + ((r-8)>>1), gate = 2+((r-8)&1)
        int k = idx / (G4 * HD);
        int rem = idx - k * (G4 * HD);
        int j = rem >> 8, h = rem & 255;
        int group = j >> 4, r = j & 15;
        int f, gate;
        if (r < 8) { f = group * 4 + (r >> 1); gate = r & 1; }
        else       { int r8 = r - 8; f = group * 4 + (r8 >> 1); gate = 2 + (r8 & 1); }
        int src = gate * 256 + f;
        g_wih_p[k][j * 256 + h] = __float2half(w_ih[(size_t)k * G4 * HD + src * 256 + h]);
        g_whh_p[k][j * 256 + h] = __float2half(w_hh[(size_t)k * G4 * HD + src * 256 + h]);
        if (h == 0) g_b_p[k][j] = b_ih[k * G4 + src] + b_hh[k * G4 + src];
    }
}

// ---------------- prep: one streaming pass over adj (8 j per thread, 16B stores) ----------------
__global__ void prep_kernel(const int* __restrict__ adj, float* __restrict__ out_adj) {
    const int i = blockIdx.x;
    const int tid = threadIdx.x;
    const int* row = adj + (size_t)i * NNODE * KEXP;
    float* orow = out_adj + (size_t)i * NNODE * KEXP;
    __half* A0 = &g_Ah[0][(size_t)i * NNODE];
    __half* A1 = &g_Ah[1][(size_t)i * NNODE];
    __half* A2 = &g_Ah[2][(size_t)i * NNODE];
    float s0 = 0.f, s1 = 0.f, s2 = 0.f;
    for (int j8 = tid * 8; j8 < NNODE; j8 += 2048) {
        int4 w[6];
        #pragma unroll
        for (int q = 0; q < 6; q++) w[q] = __ldcs((const int4*)(row + j8 * 3) + q);
        const int* aw = (const int*)w;
        float v[8][3];
        #pragma unroll
        for (int e = 0; e < 8; e++) {
            int j = j8 + e;
            #pragma unroll
            for (int c = 0; c < 3; c++) {
                float val = aw[e * 3 + c] ? 1.f : 0.f;
                if (j == i) val += 1.f;
                v[e][c] = val;
            }
            s0 += v[e][0]; s1 += v[e][1]; s2 += v[e][2];
        }
        #pragma unroll
        for (int q = 0; q < 6; q++) {
            float4 o = make_float4((float)aw[q * 4 + 0], (float)aw[q * 4 + 1],
                                   (float)aw[q * 4 + 2], (float)aw[q * 4 + 3]);
            __stcs((float4*)(orow + j8 * 3) + q, o);
        }
        uint4 u0 = make_uint4(
            h2bits(__floats2half2_rn(v[0][0], v[1][0])), h2bits(__floats2half2_rn(v[2][0], v[3][0])),
            h2bits(__floats2half2_rn(v[4][0], v[5][0])), h2bits(__floats2half2_rn(v[6][0], v[7][0])));
        uint4 u1 = make_uint4(
            h2bits(__floats2half2_rn(v[0][1], v[1][1])), h2bits(__floats2half2_rn(v[2][1], v[3][1])),
            h2bits(__floats2half2_rn(v[4][1], v[5][1])), h2bits(__floats2half2_rn(v[6][1], v[7][1])));
        uint4 u2 = make_uint4(
            h2bits(__floats2half2_rn(v[0][2], v[1][2])), h2bits(__floats2half2_rn(v[2][2], v[3][2])),
            h2bits(__floats2half2_rn(v[4][2], v[5][2])), h2bits(__floats2half2_rn(v[6][2], v[7][2])));
        *(uint4*)(A0 + j8) = u0;
        *(uint4*)(A1 + j8) = u1;
        *(uint4*)(A2 + j8) = u2;
    }
    __shared__ float sh[3][256];
    sh[0][tid] = s0; sh[1][tid] = s1; sh[2][tid] = s2;
    __syncthreads();
    for (int off = 128; off > 0; off >>= 1) {
        if (tid < off) {
            sh[0][tid] += sh[0][tid + off];
            sh[1][tid] += sh[1][tid + off];
            sh[2][tid] += sh[2][tid + off];
        }
        __syncthreads();
    }
    if (tid < 3) g_dinv[tid][i] = rsqrtf(sh[tid][0]);
}

// ---------------- fp16 tensor-core GEMM (NT), cp.async pipelined, ldmatrix ----------------
// C[M,Nn] = A[M,Kd] @ B[Nn,Kd]^T.  Block tile BM x 128 x BK, 256 thr = (2 x 4) warps.
// EPI: 1=LSTM gate (pair-block, staged) | 2=fc fuse | 3=half out rowscale+bias |
//      5=half gx write + LSTM init (pair-block, staged) | 6=half out colscale
template <int BM, int BK, int NST, int EPI, int MAXCTA>
__global__ void __launch_bounds__(256, MAXCTA) mma_gemm(
    const __half* __restrict__ A, size_t sA,
    const __half* __restrict__ B, size_t sB,
    const float* __restrict__ rowscale,
    const float* __restrict__ bias, int sBias,
    void* __restrict__ Cv, size_t sC,
    const __half* __restrict__ gx,    // EPI=1 (half, pair-block)
    float* __restrict__ cbuf,         // EPI=1,5
    __half* __restrict__ hout,        // EPI=1,5
    const float* __restrict__ x,      // EPI=2
    float* __restrict__ delta,        // EPI=2
    float* __restrict__ zbar,         // EPI=2
    int Nn, int Kd) {

    constexpr int MT = BM / 32;
    constexpr int LD = BK + 8;
    constexpr int AS_STAGE = BM * LD;
    constexpr int BS_STAGE = 128 * LD;
    constexpr int CPR = BK / 8;
    constexpr int ACH = BM * CPR / 256;
    constexpr int BCH = 128 * CPR / 256;
    constexpr int KS = BK / 16;
    constexpr bool STAGED = (EPI == 1 || EPI == 5);

    extern __shared__ __half smem[];
    __half* As = smem;
    __half* Bs = smem + NST * AS_STAGE;
    float* c_stage = (float*)(smem + NST * (AS_STAGE + BS_STAGE));  // [BM][32] (EPI 1/5)
    __half* h_tile = smem;                                           // overlays As post-loop

    const int z = blockIdx.z;
    A += (size_t)z * sA;
    B += (size_t)z * sB;
    float* Cf = (float*)Cv;
    __half* Ch = (__half*)Cv;
    if (EPI == 3 || EPI == 5 || EPI == 6) Ch += (size_t)z * sC;
    if (rowscale) rowscale += z * NNODE;
    if (bias) bias += z * sBias;
    if (EPI == 1) gx += (size_t)z * NG4;
    if (STAGED) { cbuf += (size_t)z * NF; hout += (size_t)z * NF; }
    if (EPI == 2) delta += (size_t)z * NF;

    const int tid = threadIdx.x;
    const int wid = tid >> 5, lane = tid & 31;
    const int warp_m = wid >> 2;
    const int warp_n = wid & 3;
    const int g = lane >> 2, c4 = lane & 3;
    const int bm = blockIdx.y * BM, bn = blockIdx.x * 128;
    const int fbase = bn >> 2;    // feature base (32 feats per 128 cols)

    const int nIter = Kd / BK;

    const int a_row = lane & 15;
    const int a_col = (lane >> 4) << 3;
    const int b_row = ((lane >> 4) << 3) + (lane & 7);
    const int b_col = ((lane >> 3) & 1) << 3;

    // EPI=1: prefetch prior c tile (coalesced) overlapped with mainloop
    if (EPI == 1) {
        #pragma unroll
        for (int q = 0; q < BM * 8 / 256; q++) {
            int id = tid + 256 * q;
            int m = id >> 3, c = id & 7;
            cp16(c_stage + m * 32 + c * 4, cbuf + (size_t)(bm + m) * HD + fbase + c * 4);
        }
        cp_commit();
    }

    auto issue = [&](int p, int it) {
        const int k0 = it * BK;
        #pragma unroll
        for (int q = 0; q < ACH; q++) {
            int id = tid + 256 * q;
            int m = id / CPR, c = id % CPR;
            cp16(As + p * AS_STAGE + m * LD + c * 8,
                 A + (size_t)(bm + m) * Kd + k0 + c * 8);
        }
        #pragma unroll
        for (int q = 0; q < BCH; q++) {
            int id = tid + 256 * q;
            int n = id / CPR, c = id % CPR;
            cp16(Bs + p * BS_STAGE + n * LD + c * 8,
                 B + (size_t)(bn + n) * Kd + k0 + c * 8);
        }
    };

    float acc[MT][4][4] = {};

    #pragma unroll
    for (int s = 0; s < NST - 1; s++) {
        if (s < nIter) issue(s, s);
        cp_commit();
    }

    for (int i = 0; i < nIter; i++) {
        const int p = i % NST;
        if (i + NST - 1 < nIter) issue((i + NST - 1) % NST, i + NST - 1);
        cp_commit();
        cp_wait<NST - 1>();
        __syncthreads();

        const __half* Ab = As + p * AS_STAGE;
        const __half* Bb = Bs + p * BS_STAGE;
        #pragma unroll
        for (int ks = 0; ks < KS; ks++) {
            const int kb = ks * 16;
            uint32_t af[MT][4], bf[4][2];
            #pragma unroll
            for (int mt = 0; mt < MT; mt++) {
                const __half* pa = Ab + (warp_m * (BM / 2) + mt * 16 + a_row) * LD + kb + a_col;
                ldsm4(af[mt][0], af[mt][1], af[mt][2], af[mt][3], pa);
            }
            #pragma unroll
            for (int q = 0; q < 2; q++) {
                const __half* pb = Bb + (warp_n * 32 + q * 16 + b_row) * LD + kb + b_col;
                ldsm4(bf[2 * q][0], bf[2 * q][1], bf[2 * q + 1][0], bf[2 * q + 1][1], pb);
            }
            #pragma unroll
            for (int mt = 0; mt < MT; mt++)
                #pragma unroll
                for (int nt = 0; nt < 4; nt++)
                    mma_f16(acc[mt][nt], af[mt], bf[nt]);
        }
        __syncthreads();
    }

    // ---- epilogue ----
    if (STAGED) {
        // pair-block gates: nt even holds (i,f), nt odd holds (g,o) of SAME features
        #pragma unroll
        for (int mt = 0; mt < MT; mt++) {
            #pragma unroll
            for (int p = 0; p < 2; p++) {
                const int cif = bn + warp_n * 32 + p * 16 + c4 * 2;
                const int cgo = cif + 8;
                #pragma unroll
                for (int rr = 0; rr < 2; rr++) {
                    const int row = bm + warp_m * (BM / 2) + mt * 16 + g + rr * 8;
                    float si = acc[mt][2 * p][rr * 2 + 0];
                    float sf = acc[mt][2 * p][rr * 2 + 1];
                    float sg = acc[mt][2 * p + 1][rr * 2 + 0];
                    float so = acc[mt][2 * p + 1][rr * 2 + 1];
                    if (EPI == 5) {
                        si += bias[cif]; sf += bias[cif + 1];
                        sg += bias[cgo]; so += bias[cgo + 1];
                        *(__half2*)(Ch + (size_t)row * Nn + cif) = __floats2half2_rn(si, sf);
                        *(__half2*)(Ch + (size_t)row * Nn + cgo) = __floats2half2_rn(sg, so);
                    } else {
                        __half2 gif = *(const __half2*)(gx + (size_t)row * G4 + cif);
                        __half2 ggo = *(const __half2*)(gx + (size_t)row * G4 + cgo);
                        si += __half2float(gif.x); sf += __half2float(gif.y);
                        sg += __half2float(ggo.x); so += __half2float(ggo.y);
                    }
                    const int sl = (row - bm) * 32 + warp_n * 8 + p * 4 + c4;
                    float cn;
                    if (EPI == 5) cn = fsig(si) * ftanh(sg);
                    else          cn = fsig(sf) * c_stage[sl] + fsig(si) * ftanh(sg);
                    c_stage[sl] = cn;
                    h_tile[sl] = __float2half(fsig(so) * ftanh(cn));
                }
            }
        }
        __syncthreads();
        #pragma unroll
        for (int q = 0; q < BM * 32 / 256; q++) {
            int id = tid + 256 * q;
            int rl = id >> 5, cc = id & 31;
            cbuf[(size_t)(bm + rl) * HD + fbase + cc] = c_stage[rl * 32 + cc];
            hout[(size_t)(bm + rl) * HD + fbase + cc] = h_tile[rl * 32 + cc];
        }
    } else {
        #pragma unroll
        for (int mt = 0; mt < MT; mt++) {
            #pragma unroll
            for (int nt = 0; nt < 4; nt++) {
                const int col = bn + warp_n * 32 + nt * 8 + c4 * 2;
                #pragma unroll
                for (int rr = 0; rr < 2; rr++) {
                    const int row = bm + warp_m * (BM / 2) + mt * 16 + g + rr * 8;
                    float v0 = acc[mt][nt][rr * 2 + 0];
                    float v1 = acc[mt][nt][rr * 2 + 1];
                    if (EPI == 2) {
                        v0 += bias[col]; v1 += bias[col + 1];
                        float d0 = ftanh(v0), d1 = ftanh(v1);
                        size_t ix = (size_t)row * FD + col;
                        delta[ix] = d0; delta[ix + 1] = d1;
                        float z0 = x[ix] + d0, z1 = x[ix + 1] + d1;
                        if (col >= SIG_LO && col < SIG_HI) z0 = fsig(z0);
                        if (col + 1 >= SIG_LO && col + 1 < SIG_HI) z1 = fsig(z1);
                        zbar[ix * KEXP + z] = z0;
                        zbar[(ix + 1) * KEXP + z] = z1;
                    } else if (EPI == 3) {
                        float s = rowscale[row];
                        v0 = v0 * s + bias[col];
                        v1 = v1 * s + bias[col + 1];
                        *(__half2*)(Ch + (size_t)row * Nn + col) = __floats2half2_rn(v0, v1);
                    } else {  // EPI == 6
                        v0 *= rowscale[col];
                        v1 *= rowscale[col + 1];
                        *(__half2*)(Ch + (size_t)row * Nn + col) = __floats2half2_rn(v0, v1);
                    }
                }
            }
        }
    }
}

// ---------------- final prediction ----------------
__global__ void final_pred(const float* __restrict__ x, float* __restrict__ out_pred) {
    int idx = blockIdx.x * 256 + threadIdx.x;
    int f = idx & 255;
    float d = (g_delta[0][idx] + g_delta[1][idx] + g_delta[2][idx]) * (1.0f / 3.0f);
    float z = x[idx] + d;
    if (f >= SIG_LO && f < SIG_HI) z = fsig(z);
    out_pred[idx] = z;
}

// ---------------- launcher ----------------
extern "C" void kernel_launch(void* const* d_in, const int* in_sizes, int n_in,
                              void* d_out, int out_size) {
    const float* x     = (const float*)d_in[0];
    const float* gnn_w = (const float*)d_in[1];
    const float* gnn_b = (const float*)d_in[2];
    const float* w_ih  = (const float*)d_in[3];
    const float* w_hh  = (const float*)d_in[4];
    const float* b_ih  = (const float*)d_in[5];
    const float* b_hh  = (const float*)d_in[6];
    const float* fc_w  = (const float*)d_in[7];
    const float* fc_b  = (const float*)d_in[8];
    const int*   adj   = (const int*)d_in[9];

    float* out = (float*)d_out;
    float* out_pred = out;
    float* out_zbar = out + NF;
    float* out_adj  = out + NF * 4;

    __half *p_Ah, *p_yT, *p_xt, *p_gxh, *p_h0, *p_h1, *p_wih, *p_whh, *p_wT, *p_fcw, *p_xh;
    float *p_dinv, *p_c, *p_delta, *p_bp;
    cudaGetSymbolAddress((void**)&p_Ah,    g_Ah);
    cudaGetSymbolAddress((void**)&p_dinv,  g_dinv);
    cudaGetSymbolAddress((void**)&p_yT,    g_yT);
    cudaGetSymbolAddress((void**)&p_xt,    g_xt);
    cudaGetSymbolAddress((void**)&p_gxh,   g_gx);
    cudaGetSymbolAddress((void**)&p_h0,    g_h);
    p_h1 = p_h0 + KEXP * NF;
    cudaGetSymbolAddress((void**)&p_c,     g_c);
    cudaGetSymbolAddress((void**)&p_delta, g_delta);
    cudaGetSymbolAddress((void**)&p_wih,   g_wih_p);
    cudaGetSymbolAddress((void**)&p_whh,   g_whh_p);
    cudaGetSymbolAddress((void**)&p_bp,    g_b_p);
    cudaGetSymbolAddress((void**)&p_wT,    g_wT);
    cudaGetSymbolAddress((void**)&p_fcw,   g_fcw);
    cudaGetSymbolAddress((void**)&p_xh,    g_xh);

    const int smem_yT     = 2 * (64 + 128) * 72 * 2;                  // 55296
    const int smem_gcn    = 2 * (64 + 128) * 72 * 2;                  // 55296
    const int smem_lstm64 = 2 * (64 + 128) * 72 * 2 + 64 * 32 * 4;    // 63488
    const int smem_fc     = 2 * (64 + 128) * 72 * 2;                  // 55296
    cudaFuncSetAttribute((const void*)&mma_gemm<64, 64, 2, 6, 3>, cudaFuncAttributeMaxDynamicSharedMemorySize, smem_yT);
    cudaFuncSetAttribute((const void*)&mma_gemm<64, 64, 2, 3, 3>, cudaFuncAttributeMaxDynamicSharedMemorySize, smem_gcn);
    cudaFuncSetAttribute((const void*)&mma_gemm<64, 64, 2, 5, 3>, cudaFuncAttributeMaxDynamicSharedMemorySize, smem_lstm64);
    cudaFuncSetAttribute((const void*)&mma_gemm<64, 64, 2, 1, 3>, cudaFuncAttributeMaxDynamicSharedMemorySize, smem_lstm64);
    cudaFuncSetAttribute((const void*)&mma_gemm<64, 64, 2, 2, 3>, cudaFuncAttributeMaxDynamicSharedMemorySize, smem_fc);

    const dim3 blk(256);

    // (1) conversions (merged)
    conv_all<<<(int)(NF / 256), 256>>>(x, gnn_w, fc_w, w_ih, w_hh, b_ih, b_hh);
    // (2) prep (widened stores)
    prep_kernel<<<NNODE, 256>>>(adj, out_adj);

    // (3) yT[h][n] = dinv[n] * sum_f wT[h][f] x[n][f]
    mma_gemm<64, 64, 2, 6, 3><<<dim3(32, 4, 3), blk, smem_yT>>>(
        p_wT, (size_t)FD * HD, p_xh, 0, p_dinv, nullptr, 0,
        p_yT, (size_t)HD * NNODE, nullptr, nullptr, nullptr, nullptr, nullptr, nullptr,
        NNODE, FD);

    // (4) GCN: xt = dinv * (A @ y) + gnn_b  <- ncu-captured
    mma_gemm<64, 64, 2, 3, 3><<<dim3(2, 64, 3), blk, smem_gcn>>>(
        p_Ah, (size_t)NNODE * NNODE, p_yT, (size_t)HD * NNODE, p_dinv, gnn_b, HD,
        p_xt, NF, nullptr, nullptr, nullptr, nullptr, nullptr, nullptr, HD, NNODE);

    // (5) gx = xt @ wih_p^T + b_p (half, pair-block) ; fused LSTM t=0
    mma_gemm<64, 64, 2, 5, 3><<<dim3(8, 64, 3), blk, smem_lstm64>>>(
        p_xt, NF, p_wih, (size_t)G4 * HD, nullptr, p_bp, G4,
        p_gxh, NG4, nullptr, p_c, p_h0, nullptr, nullptr, nullptr, G4, HD);

    // (6-9) t = 1..4 : fused GEMM + gate
    __half* hbuf[2] = { p_h0, p_h1 };
    for (int t = 1; t < TSTEP; t++) {
        __half* hin  = hbuf[(t - 1) & 1];
        __half* hout = hbuf[t & 1];
        mma_gemm<64, 64, 2, 1, 3><<<dim3(8, 64, 3), blk, smem_lstm64>>>(
            hin, NF, p_whh, (size_t)G4 * HD, nullptr, nullptr, 0,
            nullptr, 0, p_gxh, p_c, hout, nullptr, nullptr, nullptr, G4, HD);
    }

    // (10) fc: delta = tanh(h @ fc_w^T + fc_b); zbar fused
    mma_gemm<64, 64, 2, 2, 3><<<dim3(2, 64, 3), blk, smem_fc>>>(
        hbuf[(TSTEP - 1) & 1], NF, p_fcw, (size_t)FD * HD, nullptr, fc_b, FD,
        nullptr, 0, nullptr, nullptr, nullptr, x, p_delta, out_zbar, FD, HD);

    // (11) final
    final_pred<<<(int)(NF / 256), 256>>>(x, out_pred);
}

// round 16
// speedup vs baseline: 1.1056x; 1.1056x over previous
#include <cuda_runtime.h>
#include <cuda_fp16.h>
#include <cstdint>

#define NNODE 4096
#define FD 256
#define HD 256
#define KEXP 3
#define TSTEP 5
#define G4 1024
#define SIG_LO 10
#define SIG_HI 253   // F_DIM - END

#define NF  ((size_t)NNODE * FD)     // 1048576
#define NG4 ((size_t)NNODE * G4)

// ---------------- scratch (device globals: no allocation allowed) ----------------
__device__ __half g_Ah[KEXP][(size_t)NNODE * NNODE];  // a_bin + I, {0,1,2} exact
__device__ float  g_dinv[KEXP][NNODE];
__device__ __half g_yT[KEXP][(size_t)HD * NNODE];     // (dinv_j * x@w)^T  [h][n]
__device__ __half g_xt[KEXP][NF];                     // gnn_out, half, row-major
__device__ __half g_gx[KEXP][NG4];                    // pair-block gate layout, half
__device__ __half g_h[2][KEXP][NF];                   // double-buffered hidden
__device__ float  g_c[KEXP][NF];
__device__ float  g_delta[KEXP][NF];
__device__ __half g_wih_p[KEXP][G4 * HD];             // pair-block permuted, half
__device__ __half g_whh_p[KEXP][G4 * HD];
__device__ float  g_b_p[KEXP][G4];                    // b_ih + b_hh permuted
__device__ __half g_wT[KEXP][FD * HD];                // gnn_w transposed [h][f]
__device__ __half g_fcw[KEXP][FD * HD];               // fc_w cast (already [n][k])
__device__ __half g_xh[NF];                           // x cast

// hardware tanh (sm_75+): 1 MUFU op, abs err ~1e-5
__device__ __forceinline__ float ftanh(float x) {
    float y;
    asm("tanh.approx.f32 %0, %1;" : "=f"(y) : "f"(x));
    return y;
}
__device__ __forceinline__ float fsig(float x) {
    return fmaf(ftanh(x * 0.5f), 0.5f, 0.5f);
}

__device__ __forceinline__ void mma_f16(float c[4], const uint32_t a[4], const uint32_t b[2]) {
    asm volatile(
        "mma.sync.aligned.m16n8k16.row.col.f32.f16.f16.f32 "
        "{%0,%1,%2,%3}, {%4,%5,%6,%7}, {%8,%9}, {%0,%1,%2,%3};"
        : "+f"(c[0]), "+f"(c[1]), "+f"(c[2]), "+f"(c[3])
        : "r"(a[0]), "r"(a[1]), "r"(a[2]), "r"(a[3]), "r"(b[0]), "r"(b[1]));
}

__device__ __forceinline__ void cp16(void* sdst, const void* gsrc) {
    uint32_t s = (uint32_t)__cvta_generic_to_shared(sdst);
    asm volatile("cp.async.cg.shared.global [%0], [%1], 16;\n" :: "r"(s), "l"(gsrc));
}
__device__ __forceinline__ void cp_commit() { asm volatile("cp.async.commit_group;\n"); }
template <int N>
__device__ __forceinline__ void cp_wait() { asm volatile("cp.async.wait_group %0;\n" :: "n"(N)); }

__device__ __forceinline__ void ldsm4(uint32_t& r0, uint32_t& r1, uint32_t& r2, uint32_t& r3,
                                      const __half* p) {
    uint32_t a = (uint32_t)__cvta_generic_to_shared(p);
    asm volatile("ldmatrix.sync.aligned.m8n8.x4.shared.b16 {%0,%1,%2,%3}, [%4];"
                 : "=r"(r0), "=r"(r1), "=r"(r2), "=r"(r3) : "r"(a));
}

__device__ __forceinline__ uint32_t h2bits(__half2 h) { return *(uint32_t*)&h; }

// ---------------- conversions (3 kernels, round-14 config) ----------------
__global__ void conv_x(const float* __restrict__ x) {
    int idx = blockIdx.x * 256 + threadIdx.x;
    g_xh[idx] = __float2half(x[idx]);
}

__global__ void conv_w(const float* __restrict__ gnn_w, const float* __restrict__ fc_w) {
    int idx = blockIdx.x * 256 + threadIdx.x;   // < KEXP*FD*HD
    int k = idx / (FD * HD);
    int rem = idx - k * (FD * HD);
    int f = rem / HD, h = rem % HD;
    g_wT[k][h * FD + f] = __float2half(gnn_w[idx]);
    g_fcw[k][rem] = __float2half(fc_w[idx]);
}

// pair-block gate permutation:
// out row j: group=j>>4, r=j&15.
//  r<8 : f = group*4 + (r>>1), gate = r&1
//  r>=8: f = group*4 + ((r-8)>>1), gate = 2+((r-8)&1)
__global__ void permute_w(const float* __restrict__ w_ih, const float* __restrict__ w_hh,
                          const float* __restrict__ b_ih, const float* __restrict__ b_hh) {
    int idx = blockIdx.x * 256 + threadIdx.x;   // < KEXP*G4*HD
    int k = idx / (G4 * HD);
    int rem = idx - k * (G4 * HD);
    int j = rem >> 8, h = rem & 255;
    int group = j >> 4, r = j & 15;
    int f, gate;
    if (r < 8) { f = group * 4 + (r >> 1); gate = r & 1; }
    else       { int r8 = r - 8; f = group * 4 + (r8 >> 1); gate = 2 + (r8 & 1); }
    int src = gate * 256 + f;
    g_wih_p[k][j * 256 + h] = __float2half(w_ih[(size_t)k * G4 * HD + src * 256 + h]);
    g_whh_p[k][j * 256 + h] = __float2half(w_hh[(size_t)k * G4 * HD + src * 256 + h]);
    if (h == 0) g_b_p[k][j] = b_ih[k * G4 + src] + b_hh[k * G4 + src];
}

// ---------------- prep: smem-staged, fully coalesced global access ----------------
// Row = 4096 j * 3 ints = 3072 int4. Process 4 chunks of 768 int4 (1024 j).
__global__ void prep_kernel(const int* __restrict__ adj, float* __restrict__ out_adj) {
    const int i = blockIdx.x;
    const int tid = threadIdx.x;
    const int4* rowv = (const int4*)(adj + (size_t)i * NNODE * KEXP);
    float4* orov = (float4*)(out_adj + (size_t)i * NNODE * KEXP);
    __half* A0 = &g_Ah[0][(size_t)i * NNODE];
    __half* A1 = &g_Ah[1][(size_t)i * NNODE];
    __half* A2 = &g_Ah[2][(size_t)i * NNODE];

    __shared__ int4 sm4[768];          // 12 KB stage
    __shared__ float sh[3][256];

    float s0 = 0.f, s1 = 0.f, s2 = 0.f;

    for (int ch = 0; ch < 4; ch++) {
        // (a) coalesced stage: 768 int4, stride-1
        #pragma unroll
        for (int s = 0; s < 3; s++) {
            int idx = tid + 256 * s;
            sm4[idx] = __ldcs(rowv + ch * 768 + idx);
        }
        __syncthreads();
        // (b) coalesced adj passthrough (position-identical int->float)
        #pragma unroll
        for (int s = 0; s < 3; s++) {
            int idx = tid + 256 * s;
            int4 w = sm4[idx];
            __stcs(orov + ch * 768 + idx,
                   make_float4((float)w.x, (float)w.y, (float)w.z, (float)w.w));
        }
        // (c) per-j A build + degree from smem
        {
            const int j0 = ch * 1024 + tid * 4;
            const int* sw = (const int*)sm4 + tid * 12;
            float v[4][3];
            #pragma unroll
            for (int e = 0; e < 4; e++) {
                int j = j0 + e;
                #pragma unroll
                for (int c = 0; c < 3; c++) {
                    float val = sw[e * 3 + c] ? 1.f : 0.f;
                    if (j == i) val += 1.f;
                    v[e][c] = val;
                }
                s0 += v[e][0]; s1 += v[e][1]; s2 += v[e][2];
            }
            uint2 u0 = make_uint2(h2bits(__floats2half2_rn(v[0][0], v[1][0])),
                                  h2bits(__floats2half2_rn(v[2][0], v[3][0])));
            uint2 u1 = make_uint2(h2bits(__floats2half2_rn(v[0][1], v[1][1])),
                                  h2bits(__floats2half2_rn(v[2][1], v[3][1])));
            uint2 u2 = make_uint2(h2bits(__floats2half2_rn(v[0][2], v[1][2])),
                                  h2bits(__floats2half2_rn(v[2][2], v[3][2])));
            *(uint2*)(A0 + j0) = u0;
            *(uint2*)(A1 + j0) = u1;
            *(uint2*)(A2 + j0) = u2;
        }
        __syncthreads();
    }

    sh[0][tid] = s0; sh[1][tid] = s1; sh[2][tid] = s2;
    __syncthreads();
    for (int off = 128; off > 0; off >>= 1) {
        if (tid < off) {
            sh[0][tid] += sh[0][tid + off];
            sh[1][tid] += sh[1][tid + off];
            sh[2][tid] += sh[2][tid + off];
        }
        __syncthreads();
    }
    if (tid < 3) g_dinv[tid][i] = rsqrtf(sh[tid][0]);
}

// ---------------- fp16 tensor-core GEMM (NT), cp.async pipelined, ldmatrix ----------------
// C[M,Nn] = A[M,Kd] @ B[Nn,Kd]^T.  Block tile BM x 128 x BK, 256 thr = (2 x 4) warps.
// EPI: 1=LSTM gate (pair-block, staged) | 2=fc fuse | 3=half out rowscale+bias |
//      5=half gx write + LSTM init (pair-block, staged) | 6=half out colscale
template <int BM, int BK, int NST, int EPI, int MAXCTA>
__global__ void __launch_bounds__(256, MAXCTA) mma_gemm(
    const __half* __restrict__ A, size_t sA,
    const __half* __restrict__ B, size_t sB,
    const float* __restrict__ rowscale,
    const float* __restrict__ bias, int sBias,
    void* __restrict__ Cv, size_t sC,
    const __half* __restrict__ gx,    // EPI=1 (half, pair-block)
    float* __restrict__ cbuf,         // EPI=1,5
    __half* __restrict__ hout,        // EPI=1,5
    const float* __restrict__ x,      // EPI=2
    float* __restrict__ delta,        // EPI=2
    float* __restrict__ zbar,         // EPI=2
    int Nn, int Kd) {

    constexpr int MT = BM / 32;
    constexpr int LD = BK + 8;
    constexpr int AS_STAGE = BM * LD;
    constexpr int BS_STAGE = 128 * LD;
    constexpr int CPR = BK / 8;
    constexpr int ACH = BM * CPR / 256;
    constexpr int BCH = 128 * CPR / 256;
    constexpr int KS = BK / 16;
    constexpr bool STAGED = (EPI == 1 || EPI == 5);

    extern __shared__ __half smem[];
    __half* As = smem;
    __half* Bs = smem + NST * AS_STAGE;
    float* c_stage = (float*)(smem + NST * (AS_STAGE + BS_STAGE));  // [BM][32] (EPI 1/5)
    __half* h_tile = smem;                                           // overlays As post-loop

    const int z = blockIdx.z;
    A += (size_t)z * sA;
    B += (size_t)z * sB;
    float* Cf = (float*)Cv;
    __half* Ch = (__half*)Cv;
    if (EPI == 3 || EPI == 5 || EPI == 6) Ch += (size_t)z * sC;
    if (rowscale) rowscale += z * NNODE;
    if (bias) bias += z * sBias;
    if (EPI == 1) gx += (size_t)z * NG4;
    if (STAGED) { cbuf += (size_t)z * NF; hout += (size_t)z * NF; }
    if (EPI == 2) delta += (size_t)z * NF;

    const int tid = threadIdx.x;
    const int wid = tid >> 5, lane = tid & 31;
    const int warp_m = wid >> 2;
    const int warp_n = wid & 3;
    const int g = lane >> 2, c4 = lane & 3;
    const int bm = blockIdx.y * BM, bn = blockIdx.x * 128;
    const int fbase = bn >> 2;    // feature base (32 feats per 128 cols)

    const int nIter = Kd / BK;

    const int a_row = lane & 15;
    const int a_col = (lane >> 4) << 3;
    const int b_row = ((lane >> 4) << 3) + (lane & 7);
    const int b_col = ((lane >> 3) & 1) << 3;

    // EPI=1: prefetch prior c tile (coalesced) overlapped with mainloop
    if (EPI == 1) {
        #pragma unroll
        for (int q = 0; q < BM * 8 / 256; q++) {
            int id = tid + 256 * q;
            int m = id >> 3, c = id & 7;
            cp16(c_stage + m * 32 + c * 4, cbuf + (size_t)(bm + m) * HD + fbase + c * 4);
        }
        cp_commit();
    }

    auto issue = [&](int p, int it) {
        const int k0 = it * BK;
        #pragma unroll
        for (int q = 0; q < ACH; q++) {
            int id = tid + 256 * q;
            int m = id / CPR, c = id % CPR;
            cp16(As + p * AS_STAGE + m * LD + c * 8,
                 A + (size_t)(bm + m) * Kd + k0 + c * 8);
        }
        #pragma unroll
        for (int q = 0; q < BCH; q++) {
            int id = tid + 256 * q;
            int n = id / CPR, c = id % CPR;
            cp16(Bs + p * BS_STAGE + n * LD + c * 8,
                 B + (size_t)(bn + n) * Kd + k0 + c * 8);
        }
    };

    float acc[MT][4][4] = {};

    #pragma unroll
    for (int s = 0; s < NST - 1; s++) {
        if (s < nIter) issue(s, s);
        cp_commit();
    }

    for (int i = 0; i < nIter; i++) {
        const int p = i % NST;
        if (i + NST - 1 < nIter) issue((i + NST - 1) % NST, i + NST - 1);
        cp_commit();
        cp_wait<NST - 1>();
        __syncthreads();

        const __half* Ab = As + p * AS_STAGE;
        const __half* Bb = Bs + p * BS_STAGE;
        #pragma unroll
        for (int ks = 0; ks < KS; ks++) {
            const int kb = ks * 16;
            uint32_t af[MT][4], bf[4][2];
            #pragma unroll
            for (int mt = 0; mt < MT; mt++) {
                const __half* pa = Ab + (warp_m * (BM / 2) + mt * 16 + a_row) * LD + kb + a_col;
                ldsm4(af[mt][0], af[mt][1], af[mt][2], af[mt][3], pa);
            }
            #pragma unroll
            for (int q = 0; q < 2; q++) {
                const __half* pb = Bb + (warp_n * 32 + q * 16 + b_row) * LD + kb + b_col;
                ldsm4(bf[2 * q][0], bf[2 * q][1], bf[2 * q + 1][0], bf[2 * q + 1][1], pb);
            }
            #pragma unroll
            for (int mt = 0; mt < MT; mt++)
                #pragma unroll
                for (int nt = 0; nt < 4; nt++)
                    mma_f16(acc[mt][nt], af[mt], bf[nt]);
        }
        __syncthreads();
    }

    // ---- epilogue ----
    if (STAGED) {
        // pair-block gates: nt even holds (i,f), nt odd holds (g,o) of SAME features
        #pragma unroll
        for (int mt = 0; mt < MT; mt++) {
            #pragma unroll
            for (int p = 0; p < 2; p++) {
                const int cif = bn + warp_n * 32 + p * 16 + c4 * 2;
                const int cgo = cif + 8;
                #pragma unroll
                for (int rr = 0; rr < 2; rr++) {
                    const int row = bm + warp_m * (BM / 2) + mt * 16 + g + rr * 8;
                    float si = acc[mt][2 * p][rr * 2 + 0];
                    float sf = acc[mt][2 * p][rr * 2 + 1];
                    float sg = acc[mt][2 * p + 1][rr * 2 + 0];
                    float so = acc[mt][2 * p + 1][rr * 2 + 1];
                    if (EPI == 5) {
                        si += bias[cif]; sf += bias[cif + 1];
                        sg += bias[cgo]; so += bias[cgo + 1];
                        *(__half2*)(Ch + (size_t)row * Nn + cif) = __floats2half2_rn(si, sf);
                        *(__half2*)(Ch + (size_t)row * Nn + cgo) = __floats2half2_rn(sg, so);
                    } else {
                        __half2 gif = *(const __half2*)(gx + (size_t)row * G4 + cif);
                        __half2 ggo = *(const __half2*)(gx + (size_t)row * G4 + cgo);
                        si += __half2float(gif.x); sf += __half2float(gif.y);
                        sg += __half2float(ggo.x); so += __half2float(ggo.y);
                    }
                    const int sl = (row - bm) * 32 + warp_n * 8 + p * 4 + c4;
                    float cn;
                    if (EPI == 5) cn = fsig(si) * ftanh(sg);
                    else          cn = fsig(sf) * c_stage[sl] + fsig(si) * ftanh(sg);
                    c_stage[sl] = cn;
                    h_tile[sl] = __float2half(fsig(so) * ftanh(cn));
                }
            }
        }
        __syncthreads();
        #pragma unroll
        for (int q = 0; q < BM * 32 / 256; q++) {
            int id = tid + 256 * q;
            int rl = id >> 5, cc = id & 31;
            cbuf[(size_t)(bm + rl) * HD + fbase + cc] = c_stage[rl * 32 + cc];
            hout[(size_t)(bm + rl) * HD + fbase + cc] = h_tile[rl * 32 + cc];
        }
    } else {
        #pragma unroll
        for (int mt = 0; mt < MT; mt++) {
            #pragma unroll
            for (int nt = 0; nt < 4; nt++) {
                const int col = bn + warp_n * 32 + nt * 8 + c4 * 2;
                #pragma unroll
                for (int rr = 0; rr < 2; rr++) {
                    const int row = bm + warp_m * (BM / 2) + mt * 16 + g + rr * 8;
                    float v0 = acc[mt][nt][rr * 2 + 0];
                    float v1 = acc[mt][nt][rr * 2 + 1];
                    if (EPI == 2) {
                        v0 += bias[col]; v1 += bias[col + 1];
                        float d0 = ftanh(v0), d1 = ftanh(v1);
                        size_t ix = (size_t)row * FD + col;
                        delta[ix] = d0; delta[ix + 1] = d1;
                        float z0 = x[ix] + d0, z1 = x[ix + 1] + d1;
                        if (col >= SIG_LO && col < SIG_HI) z0 = fsig(z0);
                        if (col + 1 >= SIG_LO && col + 1 < SIG_HI) z1 = fsig(z1);
                        zbar[ix * KEXP + z] = z0;
                        zbar[(ix + 1) * KEXP + z] = z1;
                    } else if (EPI == 3) {
                        float s = rowscale[row];
                        v0 = v0 * s + bias[col];
                        v1 = v1 * s + bias[col + 1];
                        *(__half2*)(Ch + (size_t)row * Nn + col) = __floats2half2_rn(v0, v1);
                    } else {  // EPI == 6
                        v0 *= rowscale[col];
                        v1 *= rowscale[col + 1];
                        *(__half2*)(Ch + (size_t)row * Nn + col) = __floats2half2_rn(v0, v1);
                    }
                }
            }
        }
    }
}

// ---------------- final prediction ----------------
__global__ void final_pred(const float* __restrict__ x, float* __restrict__ out_pred) {
    int idx = blockIdx.x * 256 + threadIdx.x;
    int f = idx & 255;
    float d = (g_delta[0][idx] + g_delta[1][idx] + g_delta[2][idx]) * (1.0f / 3.0f);
    float z = x[idx] + d;
    if (f >= SIG_LO && f < SIG_HI) z = fsig(z);
    out_pred[idx] = z;
}

// ---------------- launcher ----------------
extern "C" void kernel_launch(void* const* d_in, const int* in_sizes, int n_in,
                              void* d_out, int out_size) {
    const float* x     = (const float*)d_in[0];
    const float* gnn_w = (const float*)d_in[1];
    const float* gnn_b = (const float*)d_in[2];
    const float* w_ih  = (const float*)d_in[3];
    const float* w_hh  = (const float*)d_in[4];
    const float* b_ih  = (const float*)d_in[5];
    const float* b_hh  = (const float*)d_in[6];
    const float* fc_w  = (const float*)d_in[7];
    const float* fc_b  = (const float*)d_in[8];
    const int*   adj   = (const int*)d_in[9];

    float* out = (float*)d_out;
    float* out_pred = out;
    float* out_zbar = out + NF;
    float* out_adj  = out + NF * 4;

    __half *p_Ah, *p_yT, *p_xt, *p_gxh, *p_h0, *p_h1, *p_wih, *p_whh, *p_wT, *p_fcw, *p_xh;
    float *p_dinv, *p_c, *p_delta, *p_bp;
    cudaGetSymbolAddress((void**)&p_Ah,    g_Ah);
    cudaGetSymbolAddress((void**)&p_dinv,  g_dinv);
    cudaGetSymbolAddress((void**)&p_yT,    g_yT);
    cudaGetSymbolAddress((void**)&p_xt,    g_xt);
    cudaGetSymbolAddress((void**)&p_gxh,   g_gx);
    cudaGetSymbolAddress((void**)&p_h0,    g_h);
    p_h1 = p_h0 + KEXP * NF;
    cudaGetSymbolAddress((void**)&p_c,     g_c);
    cudaGetSymbolAddress((void**)&p_delta, g_delta);
    cudaGetSymbolAddress((void**)&p_wih,   g_wih_p);
    cudaGetSymbolAddress((void**)&p_whh,   g_whh_p);
    cudaGetSymbolAddress((void**)&p_bp,    g_b_p);
    cudaGetSymbolAddress((void**)&p_wT,    g_wT);
    cudaGetSymbolAddress((void**)&p_fcw,   g_fcw);
    cudaGetSymbolAddress((void**)&p_xh,    g_xh);

    const int smem_yT     = 2 * (64 + 128) * 72 * 2;                  // 55296
    const int smem_gcn    = 2 * (64 + 128) * 72 * 2;                  // 55296
    const int smem_lstm64 = 2 * (64 + 128) * 72 * 2 + 64 * 32 * 4;    // 63488
    const int smem_fc     = 2 * (64 + 128) * 72 * 2;                  // 55296
    cudaFuncSetAttribute((const void*)&mma_gemm<64, 64, 2, 6, 3>, cudaFuncAttributeMaxDynamicSharedMemorySize, smem_yT);
    cudaFuncSetAttribute((const void*)&mma_gemm<64, 64, 2, 3, 3>, cudaFuncAttributeMaxDynamicSharedMemorySize, smem_gcn);
    cudaFuncSetAttribute((const void*)&mma_gemm<64, 64, 2, 5, 3>, cudaFuncAttributeMaxDynamicSharedMemorySize, smem_lstm64);
    cudaFuncSetAttribute((const void*)&mma_gemm<64, 64, 2, 1, 3>, cudaFuncAttributeMaxDynamicSharedMemorySize, smem_lstm64);
    cudaFuncSetAttribute((const void*)&mma_gemm<64, 64, 2, 2, 3>, cudaFuncAttributeMaxDynamicSharedMemorySize, smem_fc);

    const dim3 blk(256);

    // (1-3) conversions
    conv_x<<<(int)(NF / 256), 256>>>(x);
    conv_w<<<(KEXP * FD * HD) / 256, 256>>>(gnn_w, fc_w);
    permute_w<<<(KEXP * G4 * HD) / 256, 256>>>(w_ih, w_hh, b_ih, b_hh);
    // (4) prep (smem-staged, coalesced)
    prep_kernel<<<NNODE, 256>>>(adj, out_adj);

    // (5) yT[h][n] = dinv[n] * sum_f wT[h][f] x[n][f]
    mma_gemm<64, 64, 2, 6, 3><<<dim3(32, 4, 3), blk, smem_yT>>>(
        p_wT, (size_t)FD * HD, p_xh, 0, p_dinv, nullptr, 0,
        p_yT, (size_t)HD * NNODE, nullptr, nullptr, nullptr, nullptr, nullptr, nullptr,
        NNODE, FD);

    // (6) GCN: xt = dinv * (A @ y) + gnn_b
    mma_gemm<64, 64, 2, 3, 3><<<dim3(2, 64, 3), blk, smem_gcn>>>(
        p_Ah, (size_t)NNODE * NNODE, p_yT, (size_t)HD * NNODE, p_dinv, gnn_b, HD,
        p_xt, NF, nullptr, nullptr, nullptr, nullptr, nullptr, nullptr, HD, NNODE);

    // (7) gx = xt @ wih_p^T + b_p (half, pair-block) ; fused LSTM t=0
    mma_gemm<64, 64, 2, 5, 3><<<dim3(8, 64, 3), blk, smem_lstm64>>>(
        p_xt, NF, p_wih, (size_t)G4 * HD, nullptr, p_bp, G4,
        p_gxh, NG4, nullptr, p_c, p_h0, nullptr, nullptr, nullptr, G4, HD);

    // (8-11) t = 1..4 : fused GEMM + gate
    __half* hbuf[2] = { p_h0, p_h1 };
    for (int t = 1; t < TSTEP; t++) {
        __half* hin  = hbuf[(t - 1) & 1];
        __half* hout = hbuf[t & 1];
        mma_gemm<64, 64, 2, 1, 3><<<dim3(8, 64, 3), blk, smem_lstm64>>>(
            hin, NF, p_whh, (size_t)G4 * HD, nullptr, nullptr, 0,
            nullptr, 0, p_gxh, p_c, hout, nullptr, nullptr, nullptr, G4, HD);
    }

    // (12) fc: delta = tanh(h @ fc_w^T + fc_b); zbar fused
    mma_gemm<64, 64, 2, 2, 3><<<dim3(2, 64, 3), blk, smem_fc>>>(
        hbuf[(TSTEP - 1) & 1], NF, p_fcw, (size_t)FD * HD, nullptr, fc_b, FD,
        nullptr, 0, nullptr, nullptr, nullptr, x, p_delta, out_zbar, FD, HD);

    // (13) final
    final_pred<<<(int)(NF / 256), 256>>>(x, out_pred);
}

// round 17
// speedup vs baseline: 1.1191x; 1.0122x over previous
#include <cuda_runtime.h>
#include <cuda_fp16.h>
#include <cstdint>

#define NNODE 4096
#define FD 256
#define HD 256
#define KEXP 3
#define TSTEP 5
#define G4 1024
#define SIG_LO 10
#define SIG_HI 253   // F_DIM - END

#define NF  ((size_t)NNODE * FD)     // 1048576
#define NG4 ((size_t)NNODE * G4)

// ---------------- scratch (device globals: no allocation allowed) ----------------
__device__ uint8_t g_A8[KEXP][(size_t)NNODE * NNODE]; // a_bin + I, {0,1,2} int8
__device__ float   g_dinv[KEXP][NNODE];
__device__ __half  g_yT[KEXP][(size_t)HD * NNODE];    // (dinv_j * x@w)^T  [h][n]
__device__ __half  g_xt[KEXP][NF];                    // gnn_out, half, row-major
__device__ __half  g_gx[KEXP][NG4];                   // pair-block gate layout, half
__device__ __half  g_h[2][KEXP][NF];                  // double-buffered hidden
__device__ __half  g_c[KEXP][NF];                     // cell state, half
__device__ float   g_delta[KEXP][NF];
__device__ __half  g_wih_p[KEXP][G4 * HD];            // pair-block permuted, half
__device__ __half  g_whh_p[KEXP][G4 * HD];
__device__ float   g_b_p[KEXP][G4];                   // b_ih + b_hh permuted
__device__ __half  g_wT[KEXP][FD * HD];               // gnn_w transposed [h][f]
__device__ __half  g_fcw[KEXP][FD * HD];              // fc_w cast (already [n][k])
__device__ __half  g_xh[NF];                          // x cast

// hardware tanh (sm_75+): 1 MUFU op, abs err ~1e-5
__device__ __forceinline__ float ftanh(float x) {
    float y;
    asm("tanh.approx.f32 %0, %1;" : "=f"(y) : "f"(x));
    return y;
}
__device__ __forceinline__ float fsig(float x) {
    return fmaf(ftanh(x * 0.5f), 0.5f, 0.5f);
}

__device__ __forceinline__ void mma_f16(float c[4], const uint32_t a[4], const uint32_t b[2]) {
    asm volatile(
        "mma.sync.aligned.m16n8k16.row.col.f32.f16.f16.f32 "
        "{%0,%1,%2,%3}, {%4,%5,%6,%7}, {%8,%9}, {%0,%1,%2,%3};"
        : "+f"(c[0]), "+f"(c[1]), "+f"(c[2]), "+f"(c[3])
        : "r"(a[0]), "r"(a[1]), "r"(a[2]), "r"(a[3]), "r"(b[0]), "r"(b[1]));
}

__device__ __forceinline__ void cp16(void* sdst, const void* gsrc) {
    uint32_t s = (uint32_t)__cvta_generic_to_shared(sdst);
    asm volatile("cp.async.cg.shared.global [%0], [%1], 16;\n" :: "r"(s), "l"(gsrc));
}
__device__ __forceinline__ void cp_commit() { asm volatile("cp.async.commit_group;\n"); }
template <int N>
__device__ __forceinline__ void cp_wait() { asm volatile("cp.async.wait_group %0;\n" :: "n"(N)); }

__device__ __forceinline__ void ldsm4(uint32_t& r0, uint32_t& r1, uint32_t& r2, uint32_t& r3,
                                      const __half* p) {
    uint32_t a = (uint32_t)__cvta_generic_to_shared(p);
    asm volatile("ldmatrix.sync.aligned.m8n8.x4.shared.b16 {%0,%1,%2,%3}, [%4];"
                 : "=r"(r0), "=r"(r1), "=r"(r2), "=r"(r3) : "r"(a));
}

__device__ __forceinline__ uint32_t h2bits(__half2 h) { return *(uint32_t*)&h; }

// ---------------- conversions ----------------
__global__ void conv_x(const float* __restrict__ x) {
    int idx = blockIdx.x * 256 + threadIdx.x;
    g_xh[idx] = __float2half(x[idx]);
}

__global__ void conv_w(const float* __restrict__ gnn_w, const float* __restrict__ fc_w) {
    int idx = blockIdx.x * 256 + threadIdx.x;   // < KEXP*FD*HD
    int k = idx / (FD * HD);
    int rem = idx - k * (FD * HD);
    int f = rem / HD, h = rem % HD;
    g_wT[k][h * FD + f] = __float2half(gnn_w[idx]);
    g_fcw[k][rem] = __float2half(fc_w[idx]);
}

// pair-block gate permutation
__global__ void permute_w(const float* __restrict__ w_ih, const float* __restrict__ w_hh,
                          const float* __restrict__ b_ih, const float* __restrict__ b_hh) {
    int idx = blockIdx.x * 256 + threadIdx.x;   // < KEXP*G4*HD
    int k = idx / (G4 * HD);
    int rem = idx - k * (G4 * HD);
    int j = rem >> 8, h = rem & 255;
    int group = j >> 4, r = j & 15;
    int f, gate;
    if (r < 8) { f = group * 4 + (r >> 1); gate = r & 1; }
    else       { int r8 = r - 8; f = group * 4 + (r8 >> 1); gate = 2 + (r8 & 1); }
    int src = gate * 256 + f;
    g_wih_p[k][j * 256 + h] = __float2half(w_ih[(size_t)k * G4 * HD + src * 256 + h]);
    g_whh_p[k][j * 256 + h] = __float2half(w_hh[(size_t)k * G4 * HD + src * 256 + h]);
    if (h == 0) g_b_p[k][j] = b_ih[k * G4 + src] + b_hh[k * G4 + src];
}

// ---------------- prep: smem-staged, fully coalesced; A stored int8 ----------------
__global__ void prep_kernel(const int* __restrict__ adj, float* __restrict__ out_adj) {
    const int i = blockIdx.x;
    const int tid = threadIdx.x;
    const int4* rowv = (const int4*)(adj + (size_t)i * NNODE * KEXP);
    float4* orov = (float4*)(out_adj + (size_t)i * NNODE * KEXP);
    uint8_t* A0 = &g_A8[0][(size_t)i * NNODE];
    uint8_t* A1 = &g_A8[1][(size_t)i * NNODE];
    uint8_t* A2 = &g_A8[2][(size_t)i * NNODE];

    __shared__ int4 sm4[768];
    __shared__ float sh[3][256];

    float s0 = 0.f, s1 = 0.f, s2 = 0.f;

    for (int ch = 0; ch < 4; ch++) {
        #pragma unroll
        for (int s = 0; s < 3; s++) {
            int idx = tid + 256 * s;
            sm4[idx] = __ldcs(rowv + ch * 768 + idx);
        }
        __syncthreads();
        #pragma unroll
        for (int s = 0; s < 3; s++) {
            int idx = tid + 256 * s;
            int4 w = sm4[idx];
            __stcs(orov + ch * 768 + idx,
                   make_float4((float)w.x, (float)w.y, (float)w.z, (float)w.w));
        }
        {
            const int j0 = ch * 1024 + tid * 4;
            const int* sw = (const int*)sm4 + tid * 12;
            uint8_t v[4][3];
            #pragma unroll
            for (int e = 0; e < 4; e++) {
                int j = j0 + e;
                #pragma unroll
                for (int c = 0; c < 3; c++) {
                    uint8_t val = sw[e * 3 + c] ? 1 : 0;
                    if (j == i) val += 1;
                    v[e][c] = val;
                }
                s0 += (float)v[e][0]; s1 += (float)v[e][1]; s2 += (float)v[e][2];
            }
            *(uchar4*)(A0 + j0) = make_uchar4(v[0][0], v[1][0], v[2][0], v[3][0]);
            *(uchar4*)(A1 + j0) = make_uchar4(v[0][1], v[1][1], v[2][1], v[3][1]);
            *(uchar4*)(A2 + j0) = make_uchar4(v[0][2], v[1][2], v[2][2], v[3][2]);
        }
        __syncthreads();
    }

    sh[0][tid] = s0; sh[1][tid] = s1; sh[2][tid] = s2;
    __syncthreads();
    for (int off = 128; off > 0; off >>= 1) {
        if (tid < off) {
            sh[0][tid] += sh[0][tid + off];
            sh[1][tid] += sh[1][tid + off];
            sh[2][tid] += sh[2][tid + off];
        }
        __syncthreads();
    }
    if (tid < 3) g_dinv[tid][i] = rsqrtf(sh[tid][0]);
}

// ---------------- fp16 tensor-core GEMM (NT), cp.async pipelined, ldmatrix ----------------
// EPI: 1=LSTM gate | 2=fc fuse | 3=half out rowscale+bias | 5=gx+LSTM init | 6=half out colscale
// A8=1: A operand is int8 in gmem, staged as int8, converted to half in smem (GCN).
template <int BM, int BK, int NST, int EPI, int MAXCTA, int A8>
__global__ void __launch_bounds__(256, MAXCTA) mma_gemm(
    const __half* __restrict__ A, size_t sA,
    const __half* __restrict__ B, size_t sB,
    const float* __restrict__ rowscale,
    const float* __restrict__ bias, int sBias,
    void* __restrict__ Cv, size_t sC,
    const __half* __restrict__ gx,
    __half* __restrict__ cbuf,
    __half* __restrict__ hout,
    const float* __restrict__ x,
    float* __restrict__ delta,
    float* __restrict__ zbar,
    int Nn, int Kd) {

    constexpr int MT = BM / 32;
    constexpr int LD = BK + 8;
    constexpr int AS_STAGE = BM * LD;
    constexpr int BS_STAGE = 128 * LD;
    constexpr int CPR = BK / 8;
    constexpr int ACH = BM * CPR / 256;
    constexpr int BCH = 128 * CPR / 256;
    constexpr int KS = BK / 16;
    constexpr bool STAGED = (EPI == 1 || EPI == 5);
    constexpr int A8_LD = BK + 16;               // bytes per staged int8 row
    constexpr int A8_STAGE = BM * A8_LD;         // bytes per stage

    extern __shared__ __half smem[];
    uint8_t* As8 = (uint8_t*)smem;
    __half* Ah;      // A8: single conversion buffer. !A8: staged A base.
    __half* Bs;
    if (A8) {
        Ah = (__half*)(As8 + NST * A8_STAGE);
        Bs = Ah + BM * LD;
    } else {
        Ah = smem;
        Bs = smem + NST * AS_STAGE;
    }
    __half* c_stage = smem + NST * (AS_STAGE + BS_STAGE);  // [BM][32] half (EPI 1/5)
    __half* h_tile = smem;                                  // overlays A region post-loop

    const int z = blockIdx.z;
    const uint8_t* A8base = (const uint8_t*)A;
    if (A8) A8base += (size_t)z * sA;
    else    A += (size_t)z * sA;
    B += (size_t)z * sB;
    float* Cf = (float*)Cv;
    __half* Ch = (__half*)Cv;
    if (EPI == 3 || EPI == 5 || EPI == 6) Ch += (size_t)z * sC;
    if (rowscale) rowscale += z * NNODE;
    if (bias) bias += z * sBias;
    if (EPI == 1) gx += (size_t)z * NG4;
    if (STAGED) { cbuf += (size_t)z * NF; hout += (size_t)z * NF; }
    if (EPI == 2) delta += (size_t)z * NF;

    const int tid = threadIdx.x;
    const int wid = tid >> 5, lane = tid & 31;
    const int warp_m = wid >> 2;
    const int warp_n = wid & 3;
    const int g = lane >> 2, c4 = lane & 3;
    const int bm = blockIdx.y * BM, bn = blockIdx.x * 128;
    const int fbase = bn >> 2;

    const int nIter = Kd / BK;

    const int a_row = lane & 15;
    const int a_col = (lane >> 4) << 3;
    const int b_row = ((lane >> 4) << 3) + (lane & 7);
    const int b_col = ((lane >> 3) & 1) << 3;

    // EPI=1: prefetch prior c tile (half, coalesced)
    if (EPI == 1) {
        int m = tid >> 2, c = tid & 3;     // BM*32 halves = 4KB = 256 cp16
        cp16(c_stage + m * 32 + c * 8, cbuf + (size_t)(bm + m) * HD + fbase + c * 8);
        cp_commit();
    }

    auto issue = [&](int p, int it) {
        const int k0 = it * BK;
        if (A8) {
            // BM*BK bytes / 16 / 256 threads = 1 chunk (BM=64, BK=64)
            int m = tid >> 2, c = tid & 3;
            cp16(As8 + p * A8_STAGE + m * A8_LD + c * 16,
                 A8base + (size_t)(bm + m) * Kd + k0 + c * 16);
        } else {
            #pragma unroll
            for (int q = 0; q < ACH; q++) {
                int id = tid + 256 * q;
                int m = id / CPR, c = id % CPR;
                cp16(Ah + p * AS_STAGE + m * LD + c * 8,
                     A + (size_t)(bm + m) * Kd + k0 + c * 8);
            }
        }
        #pragma unroll
        for (int q = 0; q < BCH; q++) {
            int id = tid + 256 * q;
            int n = id / CPR, c = id % CPR;
            cp16(Bs + p * BS_STAGE + n * LD + c * 8,
                 B + (size_t)(bn + n) * Kd + k0 + c * 8);
        }
    };

    float acc[MT][4][4] = {};

    #pragma unroll
    for (int s = 0; s < NST - 1; s++) {
        if (s < nIter) issue(s, s);
        cp_commit();
    }

    for (int i = 0; i < nIter; i++) {
        const int p = i % NST;
        if (i + NST - 1 < nIter) issue((i + NST - 1) % NST, i + NST - 1);
        cp_commit();
        cp_wait<NST - 1>();
        __syncthreads();

        const __half* Ab;
        if (A8) {
            // convert stage p int8 -> half into Ah (16 elements/thread)
            const uint8_t* s8 = As8 + p * A8_STAGE + (tid >> 2) * A8_LD + (tid & 3) * 16;
            __half* dh = Ah + (tid >> 2) * LD + (tid & 3) * 16;
            uint4 outv[2];
            __half* hv = (__half*)outv;
            #pragma unroll
            for (int q = 0; q < 4; q++) {
                uint32_t v = *(const uint32_t*)(s8 + 4 * q);
                hv[q * 4 + 0] = __ushort2half_rn(v & 0xFFu);
                hv[q * 4 + 1] = __ushort2half_rn((v >> 8) & 0xFFu);
                hv[q * 4 + 2] = __ushort2half_rn((v >> 16) & 0xFFu);
                hv[q * 4 + 3] = __ushort2half_rn(v >> 24);
            }
            ((uint4*)dh)[0] = outv[0];
            ((uint4*)dh)[1] = outv[1];
            __syncthreads();
            Ab = Ah;
        } else {
            Ab = Ah + p * AS_STAGE;
        }
        const __half* Bb = Bs + p * BS_STAGE;
        #pragma unroll
        for (int ks = 0; ks < KS; ks++) {
            const int kb = ks * 16;
            uint32_t af[MT][4], bf[4][2];
            #pragma unroll
            for (int mt = 0; mt < MT; mt++) {
                const __half* pa = Ab + (warp_m * (BM / 2) + mt * 16 + a_row) * LD + kb + a_col;
                ldsm4(af[mt][0], af[mt][1], af[mt][2], af[mt][3], pa);
            }
            #pragma unroll
            for (int q = 0; q < 2; q++) {
                const __half* pb = Bb + (warp_n * 32 + q * 16 + b_row) * LD + kb + b_col;
                ldsm4(bf[2 * q][0], bf[2 * q][1], bf[2 * q + 1][0], bf[2 * q + 1][1], pb);
            }
            #pragma unroll
            for (int mt = 0; mt < MT; mt++)
                #pragma unroll
                for (int nt = 0; nt < 4; nt++)
                    mma_f16(acc[mt][nt], af[mt], bf[nt]);
        }
        __syncthreads();
    }

    // ---- epilogue ----
    if (STAGED) {
        #pragma unroll
        for (int mt = 0; mt < MT; mt++) {
            #pragma unroll
            for (int p = 0; p < 2; p++) {
                const int cif = bn + warp_n * 32 + p * 16 + c4 * 2;
                const int cgo = cif + 8;
                #pragma unroll
                for (int rr = 0; rr < 2; rr++) {
                    const int row = bm + warp_m * (BM / 2) + mt * 16 + g + rr * 8;
                    float si = acc[mt][2 * p][rr * 2 + 0];
                    float sf = acc[mt][2 * p][rr * 2 + 1];
                    float sg = acc[mt][2 * p + 1][rr * 2 + 0];
                    float so = acc[mt][2 * p + 1][rr * 2 + 1];
                    if (EPI == 5) {
                        si += bias[cif]; sf += bias[cif + 1];
                        sg += bias[cgo]; so += bias[cgo + 1];
                        *(__half2*)(Ch + (size_t)row * Nn + cif) = __floats2half2_rn(si, sf);
                        *(__half2*)(Ch + (size_t)row * Nn + cgo) = __floats2half2_rn(sg, so);
                    } else {
                        __half2 gif = *(const __half2*)(gx + (size_t)row * G4 + cif);
                        __half2 ggo = *(const __half2*)(gx + (size_t)row * G4 + cgo);
                        si += __half2float(gif.x); sf += __half2float(gif.y);
                        sg += __half2float(ggo.x); so += __half2float(ggo.y);
                    }
                    const int sl = (row - bm) * 32 + warp_n * 8 + p * 4 + c4;
                    float cn;
                    if (EPI == 5) cn = fsig(si) * ftanh(sg);
                    else          cn = fsig(sf) * __half2float(c_stage[sl]) + fsig(si) * ftanh(sg);
                    c_stage[sl] = __float2half(cn);
                    h_tile[sl] = __float2half(fsig(so) * ftanh(cn));
                }
            }
        }
        __syncthreads();
        #pragma unroll
        for (int q = 0; q < BM * 32 / 256; q++) {
            int id = tid + 256 * q;
            int rl = id >> 5, cc = id & 31;
            cbuf[(size_t)(bm + rl) * HD + fbase + cc] = c_stage[rl * 32 + cc];
            hout[(size_t)(bm + rl) * HD + fbase + cc] = h_tile[rl * 32 + cc];
        }
    } else {
        #pragma unroll
        for (int mt = 0; mt < MT; mt++) {
            #pragma unroll
            for (int nt = 0; nt < 4; nt++) {
                const int col = bn + warp_n * 32 + nt * 8 + c4 * 2;
                #pragma unroll
                for (int rr = 0; rr < 2; rr++) {
                    const int row = bm + warp_m * (BM / 2) + mt * 16 + g + rr * 8;
                    float v0 = acc[mt][nt][rr * 2 + 0];
                    float v1 = acc[mt][nt][rr * 2 + 1];
                    if (EPI == 2) {
                        v0 += bias[col]; v1 += bias[col + 1];
                        float d0 = ftanh(v0), d1 = ftanh(v1);
                        size_t ix = (size_t)row * FD + col;
                        delta[ix] = d0; delta[ix + 1] = d1;
                        float z0 = x[ix] + d0, z1 = x[ix + 1] + d1;
                        if (col >= SIG_LO && col < SIG_HI) z0 = fsig(z0);
                        if (col + 1 >= SIG_LO && col + 1 < SIG_HI) z1 = fsig(z1);
                        zbar[ix * KEXP + z] = z0;
                        zbar[(ix + 1) * KEXP + z] = z1;
                    } else if (EPI == 3) {
                        float s = rowscale[row];
                        v0 = v0 * s + bias[col];
                        v1 = v1 * s + bias[col + 1];
                        *(__half2*)(Ch + (size_t)row * Nn + col) = __floats2half2_rn(v0, v1);
                    } else {  // EPI == 6
                        v0 *= rowscale[col];
                        v1 *= rowscale[col + 1];
                        *(__half2*)(Ch + (size_t)row * Nn + col) = __floats2half2_rn(v0, v1);
                    }
                }
            }
        }
    }
}

// ---------------- final prediction ----------------
__global__ void final_pred(const float* __restrict__ x, float* __restrict__ out_pred) {
    int idx = blockIdx.x * 256 + threadIdx.x;
    int f = idx & 255;
    float d = (g_delta[0][idx] + g_delta[1][idx] + g_delta[2][idx]) * (1.0f / 3.0f);
    float z = x[idx] + d;
    if (f >= SIG_LO && f < SIG_HI) z = fsig(z);
    out_pred[idx] = z;
}

// ---------------- launcher ----------------
extern "C" void kernel_launch(void* const* d_in, const int* in_sizes, int n_in,
                              void* d_out, int out_size) {
    const float* x     = (const float*)d_in[0];
    const float* gnn_w = (const float*)d_in[1];
    const float* gnn_b = (const float*)d_in[2];
    const float* w_ih  = (const float*)d_in[3];
    const float* w_hh  = (const float*)d_in[4];
    const float* b_ih  = (const float*)d_in[5];
    const float* b_hh  = (const float*)d_in[6];
    const float* fc_w  = (const float*)d_in[7];
    const float* fc_b  = (const float*)d_in[8];
    const int*   adj   = (const int*)d_in[9];

    float* out = (float*)d_out;
    float* out_pred = out;
    float* out_zbar = out + NF;
    float* out_adj  = out + NF * 4;

    uint8_t* p_A8;
    __half *p_yT, *p_xt, *p_gxh, *p_h0, *p_h1, *p_c, *p_wih, *p_whh, *p_wT, *p_fcw, *p_xh;
    float *p_dinv, *p_delta, *p_bp;
    cudaGetSymbolAddress((void**)&p_A8,    g_A8);
    cudaGetSymbolAddress((void**)&p_dinv,  g_dinv);
    cudaGetSymbolAddress((void**)&p_yT,    g_yT);
    cudaGetSymbolAddress((void**)&p_xt,    g_xt);
    cudaGetSymbolAddress((void**)&p_gxh,   g_gx);
    cudaGetSymbolAddress((void**)&p_h0,    g_h);
    p_h1 = p_h0 + KEXP * NF;
    cudaGetSymbolAddress((void**)&p_c,     g_c);
    cudaGetSymbolAddress((void**)&p_delta, g_delta);
    cudaGetSymbolAddress((void**)&p_wih,   g_wih_p);
    cudaGetSymbolAddress((void**)&p_whh,   g_whh_p);
    cudaGetSymbolAddress((void**)&p_bp,    g_b_p);
    cudaGetSymbolAddress((void**)&p_wT,    g_wT);
    cudaGetSymbolAddress((void**)&p_fcw,   g_fcw);
    cudaGetSymbolAddress((void**)&p_xh,    g_xh);

    const int smem_yT     = 2 * (64 + 128) * 72 * 2;                        // 55296
    const int smem_gcn8   = 2 * 64 * 80 + 64 * 72 * 2 + 2 * 128 * 72 * 2;   // 56320
    const int smem_lstm64 = 2 * (64 + 128) * 72 * 2 + 64 * 32 * 2;          // 59392
    const int smem_fc     = 2 * (64 + 128) * 72 * 2;                        // 55296
    cudaFuncSetAttribute((const void*)&mma_gemm<64, 64, 2, 6, 3, 0>, cudaFuncAttributeMaxDynamicSharedMemorySize, smem_yT);
    cudaFuncSetAttribute((const void*)&mma_gemm<64, 64, 2, 3, 3, 1>, cudaFuncAttributeMaxDynamicSharedMemorySize, smem_gcn8);
    cudaFuncSetAttribute((const void*)&mma_gemm<64, 64, 2, 5, 3, 0>, cudaFuncAttributeMaxDynamicSharedMemorySize, smem_lstm64);
    cudaFuncSetAttribute((const void*)&mma_gemm<64, 64, 2, 1, 3, 0>, cudaFuncAttributeMaxDynamicSharedMemorySize, smem_lstm64);
    cudaFuncSetAttribute((const void*)&mma_gemm<64, 64, 2, 2, 3, 0>, cudaFuncAttributeMaxDynamicSharedMemorySize, smem_fc);

    const dim3 blk(256);

    // (1-3) conversions
    conv_x<<<(int)(NF / 256), 256>>>(x);
    conv_w<<<(KEXP * FD * HD) / 256, 256>>>(gnn_w, fc_w);
    permute_w<<<(KEXP * G4 * HD) / 256, 256>>>(w_ih, w_hh, b_ih, b_hh);
    // (4) prep (smem-staged, int8 A)
    prep_kernel<<<NNODE, 256>>>(adj, out_adj);

    // (5) yT[h][n] = dinv[n] * sum_f wT[h][f] x[n][f]
    mma_gemm<64, 64, 2, 6, 3, 0><<<dim3(32, 4, 3), blk, smem_yT>>>(
        p_wT, (size_t)FD * HD, p_xh, 0, p_dinv, nullptr, 0,
        p_yT, (size_t)HD * NNODE, nullptr, nullptr, nullptr, nullptr, nullptr, nullptr,
        NNODE, FD);

    // (6) GCN: xt = dinv * (A @ y) + gnn_b  [int8 A, in-kernel convert]
    mma_gemm<64, 64, 2, 3, 3, 1><<<dim3(2, 64, 3), blk, smem_gcn8>>>(
        (const __half*)p_A8, (size_t)NNODE * NNODE, p_yT, (size_t)HD * NNODE, p_dinv, gnn_b, HD,
        p_xt, NF, nullptr, nullptr, nullptr, nullptr, nullptr, nullptr, HD, NNODE);

    // (7) gx = xt @ wih_p^T + b_p ; fused LSTM t=0
    mma_gemm<64, 64, 2, 5, 3, 0><<<dim3(8, 64, 3), blk, smem_lstm64>>>(
        p_xt, NF, p_wih, (size_t)G4 * HD, nullptr, p_bp, G4,
        p_gxh, NG4, nullptr, p_c, p_h0, nullptr, nullptr, nullptr, G4, HD);

    // (8-11) t = 1..4 : fused GEMM + gate
    __half* hbuf[2] = { p_h0, p_h1 };
    for (int t = 1; t < TSTEP; t++) {
        __half* hin  = hbuf[(t - 1) & 1];
        __half* hout = hbuf[t & 1];
        mma_gemm<64, 64, 2, 1, 3, 0><<<dim3(8, 64, 3), blk, smem_lstm64>>>(
            hin, NF, p_whh, (size_t)G4 * HD, nullptr, nullptr, 0,
            nullptr, 0, p_gxh, p_c, hout, nullptr, nullptr, nullptr, G4, HD);
    }

    // (12) fc: delta = tanh(h @ fc_w^T + fc_b); zbar fused
    mma_gemm<64, 64, 2, 2, 3, 0><<<dim3(2, 64, 3), blk, smem_fc>>>(
        hbuf[(TSTEP - 1) & 1], NF, p_fcw, (size_t)FD * HD, nullptr, fc_b, FD,
        nullptr, 0, nullptr, nullptr, nullptr, x, p_delta, out_zbar, FD, HD);

    // (13) final
    final_pred<<<(int)(NF / 256), 256>>>(x, out_pred);
}